// round 10
// baseline (speedup 1.0000x reference)
#include <cuda_runtime.h>

#define NN 207
#define EE 1722
#define TT 24
#define BB 64
#define LL 2048
#define RESV 12
#define L4 (LL / 4)        // 512 float4 per x row
#define COLS 256           // columns per CTA tile
#define CT4 (COLS / 4)     // 64 float4 per tile row
#define CU4 (COLS / 8)     // 32 uint4 (bf16) per tile row
#define NTHREADS 768
#define NWARPS (NTHREADS / 32)

// ---------------- device scratch (no allocation allowed) ----------------
struct __align__(16) EF { float wrn; float wra; int noff; int pad; };   // wrn = -wr
struct __align__(16) ET2 { float w0; float w1; int noff; int pad; };    // w0=w1=wda-wd

__device__ int g_offF[NN + 1];
__device__ int g_offT[NN + 1];
__device__ int g_eidF[EE];     // from-CSR slot -> edge id
__device__ int g_eidT[EE];     // to-CSR slot -> edge id
__device__ int g_noffF[EE];    // from-CSR slot -> byte offset of x[to] bf16 row (node*512)
__device__ int g_noffT[EE];    // to-CSR slot -> byte offset of x[from] bf16 row

// ---------------- packed helpers ----------------
__device__ __forceinline__ unsigned long long pk2(float a, float b) {
    unsigned long long r;
    asm("mov.b64 %0, {%1, %2};" : "=l"(r) : "f"(a), "f"(b));
    return r;
}
__device__ __forceinline__ void upk2(unsigned long long v, float& a, float& b) {
    asm("mov.b64 {%0, %1}, %2;" : "=f"(a), "=f"(b) : "l"(v));
}
__device__ __forceinline__ void fma2(unsigned long long& d,
                                     unsigned long long a, unsigned long long b) {
    asm("fma.rn.f32x2 %0, %1, %2, %0;" : "+l"(d) : "l"(a), "l"(b));
}
__device__ __forceinline__ unsigned long long bf2f2(unsigned v) {
    unsigned long long r;
    asm("{\n\t.reg .b32 lo, hi;\n\t"
        "shl.b32 lo, %1, 16;\n\t"
        "and.b32 hi, %1, 0xFFFF0000;\n\t"
        "mov.b64 %0, {lo, hi};\n\t}" : "=l"(r) : "r"(v));
    return r;
}
__device__ __forceinline__ unsigned f2bf2(float c1, float c0) {
    unsigned r;
    asm("cvt.rn.bf16x2.f32 %0, %1, %2;" : "=r"(r) : "f"(c1), "f"(c0));
    return r;
}
__device__ __forceinline__ float ftanh(float x) {
    float y;
    asm("tanh.approx.f32 %0, %1;" : "=f"(y) : "f"(x));
    return y;
}

// =====================================================================
// Mini prepass: deterministic CSR structure (t-independent). One block.
// =====================================================================
__global__ __launch_bounds__(256)
void rd_csr(const int* __restrict__ ef, const int* __restrict__ et) {
    __shared__ int sf[EE], st[EE];
    __shared__ int cntF[NN], cntT[NN], runF[NN], runT[NN];
    __shared__ int offF[NN + 1], offT[NN + 1];
    const int tid = threadIdx.x;
    const int lane = tid & 31;
    const int wid  = tid >> 5;

    for (int i = tid; i < EE; i += 256) { sf[i] = ef[i]; st[i] = et[i]; }
    for (int i = tid; i < NN; i += 256) { cntF[i] = 0; cntT[i] = 0; runF[i] = 0; runT[i] = 0; }
    __syncthreads();

    for (int i = tid; i < EE; i += 256) {
        atomicAdd(&cntF[sf[i]], 1);
        atomicAdd(&cntT[st[i]], 1);
    }
    __syncthreads();

    // warp 0: exclusive scan of cntF; warp 1: cntT
    if (wid < 2) {
        const int* cnt = wid ? cntT : cntF;
        int* off = wid ? offT : offF;
        int carry = 0;
        #pragma unroll
        for (int j = 0; j < (NN + 31) / 32; j++) {
            int idx = j * 32 + lane;
            int v = (idx < NN) ? cnt[idx] : 0;
            int s = v;
            #pragma unroll
            for (int d = 1; d < 32; d <<= 1) {
                int u = __shfl_up_sync(0xffffffffu, s, d);
                if (lane >= d) s += u;
            }
            int tot = __shfl_sync(0xffffffffu, s, 31);
            if (idx < NN) off[idx] = carry + s - v;
            carry += tot;
        }
        if (lane == 0) off[NN] = carry;
    }
    __syncthreads();

    // deterministic slot assignment via match_any ranking (edge-id order)
    if (wid < 2) {
        const int* key = wid ? st : sf;
        const int* oth = wid ? sf : st;
        const int* off = wid ? offT : offF;
        int* run  = wid ? runT : runF;
        int* eid  = wid ? g_eidT : g_eidF;
        int* noff = wid ? g_noffT : g_noffF;
        const int nch = (EE + 31) / 32;
        for (int c = 0; c < nch; c++) {
            int i = c * 32 + lane;
            int f = (i < EE) ? key[i] : (NN + lane);
            unsigned m = __match_any_sync(0xffffffffu, f);
            int leader = __ffs(m) - 1;
            int rank = __popc(m & ((1u << lane) - 1u));
            int base = 0;
            if (lane == leader && f < NN) { base = run[f]; run[f] = base + __popc(m); }
            base = __shfl_sync(0xffffffffu, base, leader);
            if (i < EE) {
                int slot = off[f] + base + rank;
                eid[slot]  = i;
                noff[slot] = oth[i] * (COLS * 2);   // byte offset of target bf16 row
            }
        }
    }
    __syncthreads();

    if (tid <= NN) { g_offF[tid] = offF[tid]; g_offT[tid] = offT[tid]; }
}

// =====================================================================
// Main kernel: 256-col tiles, 8 cols/thread, per-CTA record packing.
// smem ~164 KB -> 1 CTA/SM, 24 warps.
// =====================================================================
__global__ __launch_bounds__(NTHREADS, 1)
void rd_main(const float* __restrict__ X, const int* __restrict__ ind,
             const float* __restrict__ wr,  const float* __restrict__ wd,
             const float* __restrict__ wra, const float* __restrict__ wda,
             const float* __restrict__ br,  const float* __restrict__ bd,
             const float* __restrict__ bra, const float* __restrict__ bda,
             float* __restrict__ out) {
    extern __shared__ char sm[];
    uint4*  sxb  = reinterpret_cast<uint4*>(sm);                  // [NN*CU4] bf16 tile (105,984)
    EF*     sef  = reinterpret_cast<EF*>(sxb + NN * CU4);         // [EE] (27,552)
    ET2*    set_ = reinterpret_cast<ET2*>(sef + EE);              // [EE] (27,552)
    float4* sc1  = reinterpret_cast<float4*>(set_ + EE);          // [NN]
    float2* sc2  = reinterpret_cast<float2*>(sc1 + NN);           // [NN]
    int*    soF  = reinterpret_cast<int*>(sc2 + NN);              // [NN+1]
    int*    soT  = soF + NN + 1;                                  // [NN+1]

    const int b   = blockIdx.y;
    const int t   = ind[b] / RESV;
    const int tid = threadIdx.x;
    const int tE  = t * EE;
    const int tN  = t * NN;
    const int l0q4 = blockIdx.x * CT4;

    const float4* xb4 = reinterpret_cast<const float4*>(X)
                        + (size_t)b * 2 * NN * L4 + l0q4;

    // ---- stage bf16 x tile (256 cols) ----
    for (int idx = tid; idx < NN * CU4; idx += NTHREADS) {
        int w = idx >> 5, c = idx & (CU4 - 1);
        float4 va = xb4[(size_t)w * L4 + c * 2];
        float4 vb = xb4[(size_t)w * L4 + c * 2 + 1];
        uint4 p;
        p.x = f2bf2(va.y, va.x); p.y = f2bf2(va.w, va.z);
        p.z = f2bf2(vb.y, vb.x); p.w = f2bf2(vb.w, vb.z);
        sxb[idx] = p;
    }

    // ---- pack this t's edge records directly into smem ----
    for (int k = tid; k < EE; k += NTHREADS) {
        int e = g_eidF[k];
        EF rf; rf.wrn = -wr[tE + e]; rf.wra = wra[tE + e];
        rf.noff = g_noffF[k]; rf.pad = 0;
        sef[k] = rf;
    }
    for (int k = tid; k < EE; k += NTHREADS) {
        int e = g_eidT[k];
        float wdc = wda[tE + e] - wd[tE + e];
        ET2 rt; rt.w0 = wdc; rt.w1 = wdc; rt.noff = g_noffT[k]; rt.pad = 0;
        set_[k] = rt;
    }

    // ---- per-row coefficients (deterministic bucket-order sums) ----
    if (tid < NN) {
        const int w = tid;
        float dd1 = 1.f;
        for (int k = g_offF[w]; k < g_offF[w + 1]; k++) {
            int e = g_eidF[k];
            dd1 += wd[tE + e] + wda[tE + e];
        }
        float dr = 0.f, dra = 0.f;
        for (int k = g_offT[w]; k < g_offT[w + 1]; k++) {
            int e = g_eidT[k];
            dr += wr[tE + e]; dra += wra[tE + e];
        }
        float4 c1; c1.x = dr; c1.y = dra; c1.z = dd1; c1.w = br[tN + w];
        sc1[w] = c1;
        float2 c2; c2.x = bra[tN + w]; c2.y = bd[tN + w] + bda[tN + w];
        sc2[w] = c2;
    }
    if (tid >= 256 && tid - 256 <= NN) {
        int j = tid - 256;
        soF[j] = g_offF[j]; soT[j] = g_offT[j];
    }
    __syncthreads();

    const int lane = tid & 31;
    const int wg   = tid >> 5;
    const bool b0  = (b == 0);
    const char* sxbase = reinterpret_cast<const char*>(sxb) + lane * 16;
    float4* obase = reinterpret_cast<float4*>(out)
                    + (size_t)b * NN * L4 + l0q4 + lane * 2;

    for (int w = wg; w < NN; w += NWARPS) {
        // fp32 diag/passthrough vector — issued now, consumed after the loops
        float4 xwa = xb4[(size_t)w * L4 + lane * 2];
        float4 xwb = xb4[(size_t)w * L4 + lane * 2 + 1];

        float4 c1 = sc1[w];
        float2 c2 = sc2[w];

        unsigned long long brp  = pk2(c1.w, c1.w);
        unsigned long long brap = pk2(c2.x, c2.x);
        unsigned long long bdp  = pk2(c2.y, c2.y);
        unsigned long long r0 = brp,  r1 = brp,  r2 = brp,  r3 = brp;
        unsigned long long a0 = brap, a1 = brap, a2 = brap, a3 = brap;
        unsigned long long l0 = bdp,  l1 = bdp,  l2 = bdp,  l3 = bdp;

        int k0 = soF[w], k1 = soF[w + 1];
        #pragma unroll 2
        for (int k = k0; k < k1; k++) {
            EF e = sef[k];                                       // LDS.128 broadcast
            uint4 xv = *reinterpret_cast<const uint4*>(sxbase + e.noff);  // LDS.128 gather
            unsigned long long x0 = bf2f2(xv.x), x1 = bf2f2(xv.y);
            unsigned long long x2 = bf2f2(xv.z), x3 = bf2f2(xv.w);
            unsigned long long wrp  = pk2(e.wrn, e.wrn);
            unsigned long long wrap = pk2(e.wra, e.wra);
            fma2(r0, wrp, x0);  fma2(r1, wrp, x1);  fma2(r2, wrp, x2);  fma2(r3, wrp, x3);
            fma2(a0, wrap, x0); fma2(a1, wrap, x1); fma2(a2, wrap, x2); fma2(a3, wrap, x3);
        }

        k0 = soT[w]; k1 = soT[w + 1];
        #pragma unroll 4
        for (int k = k0; k < k1; k++) {
            ET2 e = set_[k];                                     // LDS.128 broadcast
            uint4 xv = *reinterpret_cast<const uint4*>(sxbase + e.noff);
            unsigned long long x0 = bf2f2(xv.x), x1 = bf2f2(xv.y);
            unsigned long long x2 = bf2f2(xv.z), x3 = bf2f2(xv.w);
            unsigned long long wdp = pk2(e.w0, e.w1);
            fma2(l0, wdp, x0); fma2(l1, wdp, x1); fma2(l2, wdp, x2); fma2(l3, wdp, x3);
        }

        // diagonal + passthrough in fp32 (batch 0: RWa diagonal exactly zero)
        float dra = b0 ? 0.f : c1.y;
        unsigned long long xp0 = pk2(xwa.x, xwa.y), xp1 = pk2(xwa.z, xwa.w);
        unsigned long long xp2 = pk2(xwb.x, xwb.y), xp3 = pk2(xwb.z, xwb.w);
        unsigned long long drp  = pk2(c1.x, c1.x);
        unsigned long long drap = pk2(dra,  dra );
        unsigned long long dlp  = pk2(c1.z, c1.z);
        fma2(r0, drp, xp0);  fma2(r1, drp, xp1);  fma2(r2, drp, xp2);  fma2(r3, drp, xp3);
        fma2(a0, drap, xp0); fma2(a1, drap, xp1); fma2(a2, drap, xp2); fma2(a3, drap, xp3);
        fma2(l0, dlp, xp0);  fma2(l1, dlp, xp1);  fma2(l2, dlp, xp2);  fma2(l3, dlp, xp3);

        float rr0, rr1, rr2, rr3, rr4, rr5, rr6, rr7;
        float aa0, aa1, aa2, aa3, aa4, aa5, aa6, aa7;
        float ll0, ll1, ll2, ll3, ll4, ll5, ll6, ll7;
        upk2(r0, rr0, rr1); upk2(r1, rr2, rr3); upk2(r2, rr4, rr5); upk2(r3, rr6, rr7);
        upk2(a0, aa0, aa1); upk2(a1, aa2, aa3); upk2(a2, aa4, aa5); upk2(a3, aa6, aa7);
        upk2(l0, ll0, ll1); upk2(l1, ll2, ll3); upk2(l2, ll4, ll5); upk2(l3, ll6, ll7);

        float4 o1, o2;
        o1.x = ftanh(rr0) + ftanh(aa0) + ll0;
        o1.y = ftanh(rr1) + ftanh(aa1) + ll1;
        o1.z = ftanh(rr2) + ftanh(aa2) + ll2;
        o1.w = ftanh(rr3) + ftanh(aa3) + ll3;
        o2.x = ftanh(rr4) + ftanh(aa4) + ll4;
        o2.y = ftanh(rr5) + ftanh(aa5) + ll5;
        o2.z = ftanh(rr6) + ftanh(aa6) + ll6;
        o2.w = ftanh(rr7) + ftanh(aa7) + ll7;
        obase[(size_t)w * L4]     = o1;
        obase[(size_t)w * L4 + 1] = o2;
    }
}

// ---------------- launch ----------------
extern "C" void kernel_launch(void* const* d_in, const int* in_sizes, int n_in,
                              void* d_out, int out_size) {
    const float* X   = (const float*)d_in[0];
    const int*   ind = (const int*)d_in[1];
    const int*   ef  = (const int*)d_in[2];
    const int*   et  = (const int*)d_in[3];
    const float* wr  = (const float*)d_in[4];
    const float* wd  = (const float*)d_in[5];
    const float* wra = (const float*)d_in[6];
    const float* wda = (const float*)d_in[7];
    const float* br  = (const float*)d_in[8];
    const float* bd  = (const float*)d_in[9];
    const float* bra = (const float*)d_in[10];
    const float* bda = (const float*)d_in[11];
    float* out = (float*)d_out;

    const int smem = NN * CU4 * 16        // 105,984 bf16 tile
                   + EE * 16              //  27,552 EF
                   + EE * 16              //  27,552 ET2
                   + NN * 16 + NN * 8     //   4,968 c1+c2
                   + 2 * (NN + 1) * 4;    //   1,664 offsets => 167,720 B
    cudaFuncSetAttribute(rd_main, cudaFuncAttributeMaxDynamicSharedMemorySize, smem);

    rd_csr<<<1, 256>>>(ef, et);

    dim3 grid(LL / COLS, BB);   // (8, 64)
    rd_main<<<grid, NTHREADS, smem>>>(X, ind, wr, wd, wra, wda,
                                      br, bd, bra, bda, out);
}

// round 11
// speedup vs baseline: 1.0793x; 1.0793x over previous
#include <cuda_runtime.h>

#define NN 207
#define EE 1722
#define TT 24
#define BB 64
#define LL 2048
#define RESV 12
#define L4 (LL / 4)      // 512 float4 per row
#define LT4 32           // float4 per L-tile (= 128 floats)
#define NTHREADS 512     // main kernel: 2 CTAs/SM (101 KB smem each)
#define NWARPS (NTHREADS / 32)

// ---------------- device scratch (no allocation allowed) ----------------
struct __align__(16) EF { float wrn; float wra; int noff; int pad; };  // wrn = -wr, noff = byte offset
struct __align__(8)  ET { float wdc; int noff; };

__device__ EF     g_ef[TT * EE];      // from-CSR ordered, per t (reaction gathers)
__device__ ET     g_et[TT * EE];      // to-CSR ordered, per t (diffusion gathers)
__device__ float4 g_c1[TT * NN];      // (dr, dra, dd+dda+1, br)
__device__ float2 g_c2[TT * NN];      // (bra, bd+bda)
__device__ int    g_from_off[NN + 1];
__device__ int    g_to_off[NN + 1];
__device__ int    g_eidF[EE];         // from-CSR slot -> edge id
__device__ int    g_eidT[EE];         // to-CSR slot -> edge id
__device__ int    g_noffF[EE];        // from-CSR slot -> byte off of x[to] bf16 row (node*256)
__device__ int    g_noffT[EE];        // to-CSR slot -> byte off of x[from] bf16 row

// ---------------- packed helpers ----------------
__device__ __forceinline__ unsigned long long pk2(float a, float b) {
    unsigned long long r;
    asm("mov.b64 %0, {%1, %2};" : "=l"(r) : "f"(a), "f"(b));
    return r;
}
__device__ __forceinline__ void upk2(unsigned long long v, float& a, float& b) {
    asm("mov.b64 {%0, %1}, %2;" : "=f"(a), "=f"(b) : "l"(v));
}
__device__ __forceinline__ void fma2(unsigned long long& d,
                                     unsigned long long a, unsigned long long b) {
    asm("fma.rn.f32x2 %0, %1, %2, %0;" : "+l"(d) : "l"(a), "l"(b));
}
// packed bf16 pair (hi=c1|lo=c0) -> f32x2 {lo=c0, hi=c1}  (bf16 = fp32 high bits)
__device__ __forceinline__ unsigned long long bf2f2(unsigned v) {
    unsigned long long r;
    asm("{\n\t.reg .b32 lo, hi;\n\t"
        "shl.b32 lo, %1, 16;\n\t"
        "and.b32 hi, %1, 0xFFFF0000;\n\t"
        "mov.b64 %0, {lo, hi};\n\t}" : "=l"(r) : "r"(v));
    return r;
}
// pack (c0, c1) fp32 -> bf16x2 (hi=c1, lo=c0), round-to-nearest
__device__ __forceinline__ unsigned f2bf2(float c1, float c0) {
    unsigned r;
    asm("cvt.rn.bf16x2.f32 %0, %1, %2;" : "=r"(r) : "f"(c1), "f"(c0));
    return r;
}
__device__ __forceinline__ float ftanh(float x) {
    float y;
    asm("tanh.approx.f32 %0, %1;" : "=f"(y) : "f"(x));
    return y;
}

// =====================================================================
// Prepass 1: t-independent deterministic CSR structure. One block, ~3us.
// =====================================================================
__global__ __launch_bounds__(256)
void rd_csr(const int* __restrict__ ef, const int* __restrict__ et) {
    __shared__ int sf[EE], st[EE];
    __shared__ int cntF[NN], cntT[NN], runF[NN], runT[NN];
    __shared__ int offF[NN + 1], offT[NN + 1];
    const int tid = threadIdx.x;
    const int lane = tid & 31;
    const int wid  = tid >> 5;

    for (int i = tid; i < EE; i += 256) { sf[i] = ef[i]; st[i] = et[i]; }
    for (int i = tid; i < NN; i += 256) { cntF[i] = 0; cntT[i] = 0; runF[i] = 0; runT[i] = 0; }
    __syncthreads();

    for (int i = tid; i < EE; i += 256) {
        atomicAdd(&cntF[sf[i]], 1);
        atomicAdd(&cntT[st[i]], 1);
    }
    __syncthreads();

    // warp 0: exclusive scan of cntF; warp 1: cntT
    if (wid < 2) {
        const int* cnt = wid ? cntT : cntF;
        int* off = wid ? offT : offF;
        int carry = 0;
        #pragma unroll
        for (int j = 0; j < (NN + 31) / 32; j++) {
            int idx = j * 32 + lane;
            int v = (idx < NN) ? cnt[idx] : 0;
            int s = v;
            #pragma unroll
            for (int d = 1; d < 32; d <<= 1) {
                int u = __shfl_up_sync(0xffffffffu, s, d);
                if (lane >= d) s += u;
            }
            int tot = __shfl_sync(0xffffffffu, s, 31);
            if (idx < NN) off[idx] = carry + s - v;
            carry += tot;
        }
        if (lane == 0) off[NN] = carry;
    }
    __syncthreads();

    // deterministic slot assignment via match_any ranking (edge-id order)
    if (wid < 2) {
        const int* key = wid ? st : sf;
        const int* oth = wid ? sf : st;
        const int* off = wid ? offT : offF;
        int* run  = wid ? runT : runF;
        int* eid  = wid ? g_eidT : g_eidF;
        int* noff = wid ? g_noffT : g_noffF;
        const int nch = (EE + 31) / 32;
        for (int c = 0; c < nch; c++) {
            int i = c * 32 + lane;
            int f = (i < EE) ? key[i] : (NN + lane);
            unsigned m = __match_any_sync(0xffffffffu, f);
            int leader = __ffs(m) - 1;
            int rank = __popc(m & ((1u << lane) - 1u));
            int base = 0;
            if (lane == leader && f < NN) { base = run[f]; run[f] = base + __popc(m); }
            base = __shfl_sync(0xffffffffu, base, leader);
            if (i < EE) {
                int slot = off[f] + base + rank;
                eid[slot]  = i;
                noff[slot] = oth[i] * 256;   // byte offset of target bf16 row (32 uint2)
            }
        }
    }
    __syncthreads();

    if (tid <= NN) { g_from_off[tid] = offF[tid]; g_to_off[tid] = offT[tid]; }
}

// =====================================================================
// Prepass 2: slot-parallel per-t record packing + coefficient sums.
// No scans, no ranking — embarrassingly parallel over (t, slot).
// =====================================================================
__global__ __launch_bounds__(256)
void rd_pack(const float* __restrict__ wr,  const float* __restrict__ wd,
             const float* __restrict__ wra, const float* __restrict__ wda,
             const float* __restrict__ br,  const float* __restrict__ bd,
             const float* __restrict__ bra, const float* __restrict__ bda) {
    const int t   = blockIdx.x;
    const int tid = threadIdx.x;
    const int tE  = t * EE;
    const int tN  = t * NN;

    for (int k = tid; k < EE; k += 256) {
        int e = g_eidF[k];
        EF rf; rf.wrn = -wr[tE + e]; rf.wra = wra[tE + e];
        rf.noff = g_noffF[k]; rf.pad = 0;
        g_ef[tE + k] = rf;
    }
    for (int k = tid; k < EE; k += 256) {
        int e = g_eidT[k];
        ET rt; rt.wdc = wda[tE + e] - wd[tE + e]; rt.noff = g_noffT[k];
        g_et[tE + k] = rt;
    }

    // per-row coefficients, deterministic bucket-order sums
    if (tid < NN) {
        const int w = tid;
        float dd1 = 1.f;
        for (int k = g_from_off[w]; k < g_from_off[w + 1]; k++) {
            int e = g_eidF[k];
            dd1 += wd[tE + e] + wda[tE + e];
        }
        float dr = 0.f, dra = 0.f;
        for (int k = g_to_off[w]; k < g_to_off[w + 1]; k++) {
            int e = g_eidT[k];
            dr += wr[tE + e]; dra += wra[tE + e];
        }
        float4 c1; c1.x = dr; c1.y = dra; c1.z = dd1; c1.w = br[tN + w];
        g_c1[tN + w] = c1;
        float2 c2; c2.x = bra[tN + w]; c2.y = bd[tN + w] + bda[tN + w];
        g_c2[tN + w] = c2;
    }
}

// =====================================================================
// Main kernel (R9 winner, unchanged): each CTA does TWO 128-col L-tiles,
// records staged once via cp.async, bf16 gathers, fp32 diagonal terms,
// f32x2 FFMA2 accumulation. ~101 KB smem -> 2 CTAs/SM.
// =====================================================================
__global__ __launch_bounds__(NTHREADS, 2)
void rd_main(const float* __restrict__ X, const int* __restrict__ ind,
             float* __restrict__ out) {
    extern __shared__ char smem_raw[];
    EF*     sef  = reinterpret_cast<EF*>(smem_raw);                 // [EE]
    uint2*  sxb  = reinterpret_cast<uint2*>(sef + EE);              // [NN*32] bf16 tile
    ET*     set_ = reinterpret_cast<ET*>(sxb + NN * 32);            // [EE]
    float4* sc1  = reinterpret_cast<float4*>(set_ + EE);            // [NN]
    float2* sc2  = reinterpret_cast<float2*>(sc1 + NN);             // [NN]
    int*    soF  = reinterpret_cast<int*>(sc2 + NN);                // [NN+1]
    int*    soT  = soF + NN + 1;                                    // [NN+1]

    const int b   = blockIdx.y;
    const int t   = ind[b] / RESV;
    const int tid = threadIdx.x;
    const int lane = tid & 31;
    const int wg   = tid >> 5;
    const bool b0  = (b == 0);
    const char* sxbase = reinterpret_cast<const char*>(sxb) + lane * 8;

    // ---- stage records via cp.async ONCE for both halves ----
    {
        unsigned sefA = (unsigned)__cvta_generic_to_shared(sef);
        const char* gef = (const char*)(g_ef + t * EE);
        for (int i = tid; i < EE; i += NTHREADS)
            asm volatile("cp.async.cg.shared.global [%0], [%1], 16;"
                         :: "r"(sefA + i * 16), "l"(gef + (size_t)i * 16));
        unsigned setA = (unsigned)__cvta_generic_to_shared(set_);
        const char* get = (const char*)(g_et + t * EE);
        for (int i = tid; i < EE / 2; i += NTHREADS)   // EE even: 861 x 16 B
            asm volatile("cp.async.cg.shared.global [%0], [%1], 16;"
                         :: "r"(setA + i * 16), "l"(get + (size_t)i * 16));
        asm volatile("cp.async.commit_group;");
    }
    if (tid < NN) { sc1[tid] = g_c1[t * NN + tid]; sc2[tid] = g_c2[t * NN + tid]; }
    if (tid >= NN && tid < 2 * NN + 2) {
        int j = tid - NN;
        if (j <= NN) { soF[j] = g_from_off[j]; soT[j] = g_to_off[j]; }
    }
    if (tid == 2 * NN + 2) soT[NN] = g_to_off[NN];

    #pragma unroll 1
    for (int half = 0; half < 2; half++) {
        const int l0q = (blockIdx.x * 2 + half) * LT4;
        const float4* xb4 = reinterpret_cast<const float4*>(X)
                            + (size_t)b * 2 * NN * L4 + l0q;

        // ---- stage bf16 x tile for this half ----
        for (int idx = tid; idx < NN * LT4; idx += NTHREADS) {
            int w = idx >> 5, c = idx & (LT4 - 1);
            float4 v = xb4[(size_t)w * L4 + c];
            uint2 p; p.x = f2bf2(v.y, v.x); p.y = f2bf2(v.w, v.z);
            sxb[w * 32 + c] = p;
        }
        if (half == 0) asm volatile("cp.async.wait_group 0;");
        __syncthreads();

        float4* ob4 = reinterpret_cast<float4*>(out) + (size_t)b * NN * L4 + l0q + lane;

        // row-ahead prefetch of the fp32 diagonal/passthrough vector
        float4 xw = (wg < NN) ? xb4[(size_t)wg * L4 + lane]
                              : make_float4(0.f, 0.f, 0.f, 0.f);

        for (int w = wg; w < NN; w += NWARPS) {
            // kick next row's LDG before the long LDS loops
            int wn = w + NWARPS;
            float4 xwn = xw;
            if (wn < NN) xwn = xb4[(size_t)wn * L4 + lane];

            float4 c1 = sc1[w];
            float2 c2 = sc2[w];
            float dra = b0 ? 0.f : c1.y;   // batch 0: RWa diagonal is exactly zero

            unsigned long long xw01 = pk2(xw.x, xw.y), xw23 = pk2(xw.z, xw.w);
            unsigned long long drp  = pk2(c1.x, c1.x), brp  = pk2(c1.w, c1.w);
            unsigned long long drap = pk2(dra,  dra ), brap = pk2(c2.x, c2.x);
            unsigned long long dlp  = pk2(c1.z, c1.z), bdp  = pk2(c2.y, c2.y);

            unsigned long long r01 = brp,  r23 = brp;
            unsigned long long ra01 = brap, ra23 = brap;
            unsigned long long li01 = bdp,  li23 = bdp;
            fma2(r01, drp, xw01);   fma2(r23, drp, xw23);
            fma2(ra01, drap, xw01); fma2(ra23, drap, xw23);
            fma2(li01, dlp, xw01);  fma2(li23, dlp, xw23);

            int k0 = soF[w], k1 = soF[w + 1];
            #pragma unroll 8
            for (int k = k0; k < k1; k++) {
                EF e = sef[k];                        // broadcast LDS.128 (1 wf)
                uint2 xv = *reinterpret_cast<const uint2*>(sxbase + e.noff);
                unsigned long long x01 = bf2f2(xv.x), x23 = bf2f2(xv.y);
                unsigned long long wrp  = pk2(e.wrn, e.wrn);
                unsigned long long wrap = pk2(e.wra, e.wra);
                fma2(r01, wrp, x01);   fma2(r23, wrp, x23);
                fma2(ra01, wrap, x01); fma2(ra23, wrap, x23);
            }

            k0 = soT[w]; k1 = soT[w + 1];
            #pragma unroll 8
            for (int k = k0; k < k1; k++) {
                ET e = set_[k];                       // broadcast LDS.64 (1 wf)
                uint2 xv = *reinterpret_cast<const uint2*>(sxbase + e.noff);
                unsigned long long x01 = bf2f2(xv.x), x23 = bf2f2(xv.y);
                unsigned long long wdp = pk2(e.wdc, e.wdc);
                fma2(li01, wdp, x01); fma2(li23, wdp, x23);
            }

            float r0, r1, r2, r3, a0, a1, a2, a3, l0, l1, l2, l3;
            upk2(r01, r0, r1);   upk2(r23, r2, r3);
            upk2(ra01, a0, a1);  upk2(ra23, a2, a3);
            upk2(li01, l0, l1);  upk2(li23, l2, l3);

            float4 o;
            o.x = ftanh(r0) + ftanh(a0) + l0;
            o.y = ftanh(r1) + ftanh(a1) + l1;
            o.z = ftanh(r2) + ftanh(a2) + l2;
            o.w = ftanh(r3) + ftanh(a3) + l3;
            ob4[(size_t)w * L4] = o;

            xw = xwn;
        }
        __syncthreads();   // all reads of sxb done before half=1 overwrites it
    }
}

// ---------------- launch ----------------
extern "C" void kernel_launch(void* const* d_in, const int* in_sizes, int n_in,
                              void* d_out, int out_size) {
    const float* X   = (const float*)d_in[0];
    const int*   ind = (const int*)d_in[1];
    const int*   ef  = (const int*)d_in[2];
    const int*   et  = (const int*)d_in[3];
    const float* wr  = (const float*)d_in[4];
    const float* wd  = (const float*)d_in[5];
    const float* wra = (const float*)d_in[6];
    const float* wda = (const float*)d_in[7];
    const float* br  = (const float*)d_in[8];
    const float* bd  = (const float*)d_in[9];
    const float* bra = (const float*)d_in[10];
    const float* bda = (const float*)d_in[11];
    float* out = (float*)d_out;

    const int smem  = EE * (int)sizeof(EF)          // 27,552 EF
                    + NN * 32 * (int)sizeof(uint2)  // 52,992 bf16 tile
                    + EE * (int)sizeof(ET)          // 13,776 ET
                    + NN * (int)sizeof(float4)      //  3,312 c1
                    + NN * (int)sizeof(float2)      //  1,656 c2
                    + 2 * (NN + 1) * (int)sizeof(int); // 1,664 offsets => 100,952 B
    cudaFuncSetAttribute(rd_main, cudaFuncAttributeMaxDynamicSharedMemorySize, smem);

    rd_csr<<<1, 256>>>(ef, et);
    rd_pack<<<TT, 256>>>(wr, wd, wra, wda, br, bd, bra, bda);

    dim3 grid(LL / (LT4 * 4 * 2), BB);   // (8, 64) — two L-tiles per CTA
    rd_main<<<grid, NTHREADS, smem>>>(X, ind, out);
}

// round 12
// speedup vs baseline: 1.1738x; 1.0876x over previous
#include <cuda_runtime.h>

#define NN 207
#define EE 1722
#define TT 24
#define BB 64
#define LL 2048
#define RESV 12
#define L4 (LL / 4)      // 512 float4 per row
#define LT4 32           // float4 per L-tile (= 128 floats)
#define NTHREADS 512     // main kernel: 2 CTAs/SM (101 KB smem each)
#define NWARPS (NTHREADS / 32)
#define NCH ((EE + 31) / 32)   // 54 edge chunks of 32

// ---------------- device scratch (no allocation allowed) ----------------
struct __align__(16) EF { float wrn; float wra; int noff; int pad; };  // wrn = -wr, noff = byte offset
struct __align__(8)  ET { float wdc; int noff; };

__device__ EF     g_ef[TT * EE];      // from-CSR ordered, per t (reaction gathers)
__device__ ET     g_et[TT * EE];      // to-CSR ordered, per t (diffusion gathers)
__device__ float4 g_c1[TT * NN];      // (dr, dra, dd+dda+1, br)
__device__ float2 g_c2[TT * NN];      // (bra, bd+bda)
__device__ int    g_from_off[NN + 1];
__device__ int    g_to_off[NN + 1];
__device__ int    g_eidF[EE];         // from-CSR slot -> edge id
__device__ int    g_eidT[EE];         // to-CSR slot -> edge id
__device__ int    g_noffF[EE];        // from-CSR slot -> byte off of x[to] bf16 row (node*256)
__device__ int    g_noffT[EE];        // to-CSR slot -> byte off of x[from] bf16 row

// ---------------- packed helpers ----------------
__device__ __forceinline__ unsigned long long pk2(float a, float b) {
    unsigned long long r;
    asm("mov.b64 %0, {%1, %2};" : "=l"(r) : "f"(a), "f"(b));
    return r;
}
__device__ __forceinline__ void upk2(unsigned long long v, float& a, float& b) {
    asm("mov.b64 {%0, %1}, %2;" : "=f"(a), "=f"(b) : "l"(v));
}
__device__ __forceinline__ void fma2(unsigned long long& d,
                                     unsigned long long a, unsigned long long b) {
    asm("fma.rn.f32x2 %0, %1, %2, %0;" : "+l"(d) : "l"(a), "l"(b));
}
// packed bf16 pair (hi=c1|lo=c0) -> f32x2 {lo=c0, hi=c1}  (bf16 = fp32 high bits)
__device__ __forceinline__ unsigned long long bf2f2(unsigned v) {
    unsigned long long r;
    asm("{\n\t.reg .b32 lo, hi;\n\t"
        "shl.b32 lo, %1, 16;\n\t"
        "and.b32 hi, %1, 0xFFFF0000;\n\t"
        "mov.b64 %0, {lo, hi};\n\t}" : "=l"(r) : "r"(v));
    return r;
}
// pack (c0, c1) fp32 -> bf16x2 (hi=c1, lo=c0), round-to-nearest
__device__ __forceinline__ unsigned f2bf2(float c1, float c0) {
    unsigned r;
    asm("cvt.rn.bf16x2.f32 %0, %1, %2;" : "=r"(r) : "f"(c1), "f"(c0));
    return r;
}
__device__ __forceinline__ float ftanh(float x) {
    float y;
    asm("tanh.approx.f32 %0, %1;" : "=f"(y) : "f"(x));
    return y;
}

// =====================================================================
// Prepass 1: t-independent deterministic CSR, fully chunk-parallel.
// slot(i) = off[key] + chunk_base[chunk(i)][key] + rank_within_chunk.
// One block, 1024 threads, ~105 KB dynamic smem.
// =====================================================================
__global__ __launch_bounds__(1024)
void rd_csr(const int* __restrict__ ef, const int* __restrict__ et) {
    extern __shared__ int sh[];
    int* sf   = sh;                    // [EE]
    int* st   = sf + EE;               // [EE]
    int* cF   = st + EE;               // [NCH*NN] counts -> chunk bases
    int* cT   = cF + NCH * NN;         // [NCH*NN]
    int* offF = cT + NCH * NN;         // [NN+1]
    int* offT = offF + NN + 1;         // [NN+1]
    int* totF = offT + NN + 1;         // [NN]
    int* totT = totF + NN;             // [NN]

    const int tid = threadIdx.x;
    const int lane = tid & 31;
    const int wid  = tid >> 5;

    for (int i = tid; i < EE; i += 1024) { sf[i] = ef[i]; st[i] = et[i]; }
    for (int i = tid; i < NCH * NN; i += 1024) { cF[i] = 0; cT[i] = 0; }
    __syncthreads();

    // per-(chunk, node) counts — int atomics, order-independent
    for (int i = tid; i < EE; i += 1024) {
        int c = i >> 5;
        atomicAdd(&cF[c * NN + sf[i]], 1);
        atomicAdd(&cT[c * NN + st[i]], 1);
    }
    __syncthreads();

    // per-node exclusive prefix over chunks (turn counts into chunk bases)
    if (tid < NN) {
        int run = 0;
        #pragma unroll 4
        for (int c = 0; c < NCH; c++) {
            int v = cF[c * NN + tid]; cF[c * NN + tid] = run; run += v;
        }
        totF[tid] = run;
    }
    if (tid >= 512 && tid < 512 + NN) {
        int w = tid - 512;
        int run = 0;
        #pragma unroll 4
        for (int c = 0; c < NCH; c++) {
            int v = cT[c * NN + w]; cT[c * NN + w] = run; run += v;
        }
        totT[w] = run;
    }
    __syncthreads();

    // warp 0: exclusive scan totF -> offF; warp 1: totT -> offT
    if (wid < 2) {
        const int* tot = wid ? totT : totF;
        int* off = wid ? offT : offF;
        int carry = 0;
        #pragma unroll
        for (int j = 0; j < (NN + 31) / 32; j++) {
            int idx = j * 32 + lane;
            int v = (idx < NN) ? tot[idx] : 0;
            int s = v;
            #pragma unroll
            for (int d = 1; d < 32; d <<= 1) {
                int u = __shfl_up_sync(0xffffffffu, s, d);
                if (lane >= d) s += u;
            }
            int tsum = __shfl_sync(0xffffffffu, s, 31);
            if (idx < NN) off[idx] = carry + s - v;
            carry += tsum;
        }
        if (lane == 0) off[NN] = carry;
    }
    __syncthreads();

    // chunk-parallel slot assignment: warps 0-15 F, warps 16-31 T
    {
        const bool isT = (wid >= 16);
        const int* key = isT ? st : sf;
        const int* oth = isT ? sf : st;
        const int* off = isT ? offT : offF;
        const int* cb  = isT ? cT : cF;
        int* eid  = isT ? g_eidT : g_eidF;
        int* noff = isT ? g_noffT : g_noffF;
        for (int c = (wid & 15); c < NCH; c += 16) {
            int i = c * 32 + lane;
            int f = (i < EE) ? key[i] : (NN + lane);   // distinct dummies
            unsigned m = __match_any_sync(0xffffffffu, f);
            int rank = __popc(m & ((1u << lane) - 1u));
            if (i < EE) {
                int slot = off[f] + cb[c * NN + f] + rank;
                eid[slot]  = i;
                noff[slot] = oth[i] * 256;   // byte offset of target bf16 row
            }
        }
    }
    __syncthreads();

    if (tid <= NN) { g_from_off[tid] = offF[tid]; g_to_off[tid] = offT[tid]; }
}

// =====================================================================
// Prepass 2: slot-parallel per-t record packing + coefficient sums.
// =====================================================================
__global__ __launch_bounds__(256)
void rd_pack(const float* __restrict__ wr,  const float* __restrict__ wd,
             const float* __restrict__ wra, const float* __restrict__ wda,
             const float* __restrict__ br,  const float* __restrict__ bd,
             const float* __restrict__ bra, const float* __restrict__ bda) {
    const int t   = blockIdx.x;
    const int tid = threadIdx.x;
    const int tE  = t * EE;
    const int tN  = t * NN;

    for (int k = tid; k < EE; k += 256) {
        int e = g_eidF[k];
        EF rf; rf.wrn = -wr[tE + e]; rf.wra = wra[tE + e];
        rf.noff = g_noffF[k]; rf.pad = 0;
        g_ef[tE + k] = rf;
    }
    for (int k = tid; k < EE; k += 256) {
        int e = g_eidT[k];
        ET rt; rt.wdc = wda[tE + e] - wd[tE + e]; rt.noff = g_noffT[k];
        g_et[tE + k] = rt;
    }

    // per-row coefficients, deterministic bucket-order sums
    if (tid < NN) {
        const int w = tid;
        float dd1 = 1.f;
        for (int k = g_from_off[w]; k < g_from_off[w + 1]; k++) {
            int e = g_eidF[k];
            dd1 += wd[tE + e] + wda[tE + e];
        }
        float dr = 0.f, dra = 0.f;
        for (int k = g_to_off[w]; k < g_to_off[w + 1]; k++) {
            int e = g_eidT[k];
            dr += wr[tE + e]; dra += wra[tE + e];
        }
        float4 c1; c1.x = dr; c1.y = dra; c1.z = dd1; c1.w = br[tN + w];
        g_c1[tN + w] = c1;
        float2 c2; c2.x = bra[tN + w]; c2.y = bd[tN + w] + bda[tN + w];
        g_c2[tN + w] = c2;
    }
}

// =====================================================================
// Main kernel (R9 winner, unchanged): each CTA does TWO 128-col L-tiles,
// records staged once via cp.async, bf16 gathers, fp32 diagonal terms,
// f32x2 FFMA2 accumulation. ~101 KB smem -> 2 CTAs/SM.
// =====================================================================
__global__ __launch_bounds__(NTHREADS, 2)
void rd_main(const float* __restrict__ X, const int* __restrict__ ind,
             float* __restrict__ out) {
    extern __shared__ char smem_raw[];
    EF*     sef  = reinterpret_cast<EF*>(smem_raw);                 // [EE]
    uint2*  sxb  = reinterpret_cast<uint2*>(sef + EE);              // [NN*32] bf16 tile
    ET*     set_ = reinterpret_cast<ET*>(sxb + NN * 32);            // [EE]
    float4* sc1  = reinterpret_cast<float4*>(set_ + EE);            // [NN]
    float2* sc2  = reinterpret_cast<float2*>(sc1 + NN);             // [NN]
    int*    soF  = reinterpret_cast<int*>(sc2 + NN);                // [NN+1]
    int*    soT  = soF + NN + 1;                                    // [NN+1]

    const int b   = blockIdx.y;
    const int t   = ind[b] / RESV;
    const int tid = threadIdx.x;
    const int lane = tid & 31;
    const int wg   = tid >> 5;
    const bool b0  = (b == 0);
    const char* sxbase = reinterpret_cast<const char*>(sxb) + lane * 8;

    // ---- stage records via cp.async ONCE for both halves ----
    {
        unsigned sefA = (unsigned)__cvta_generic_to_shared(sef);
        const char* gef = (const char*)(g_ef + t * EE);
        for (int i = tid; i < EE; i += NTHREADS)
            asm volatile("cp.async.cg.shared.global [%0], [%1], 16;"
                         :: "r"(sefA + i * 16), "l"(gef + (size_t)i * 16));
        unsigned setA = (unsigned)__cvta_generic_to_shared(set_);
        const char* get = (const char*)(g_et + t * EE);
        for (int i = tid; i < EE / 2; i += NTHREADS)   // EE even: 861 x 16 B
            asm volatile("cp.async.cg.shared.global [%0], [%1], 16;"
                         :: "r"(setA + i * 16), "l"(get + (size_t)i * 16));
        asm volatile("cp.async.commit_group;");
    }
    if (tid < NN) { sc1[tid] = g_c1[t * NN + tid]; sc2[tid] = g_c2[t * NN + tid]; }
    if (tid >= NN && tid < 2 * NN + 2) {
        int j = tid - NN;
        if (j <= NN) { soF[j] = g_from_off[j]; soT[j] = g_to_off[j]; }
    }
    if (tid == 2 * NN + 2) soT[NN] = g_to_off[NN];

    #pragma unroll 1
    for (int half = 0; half < 2; half++) {
        const int l0q = (blockIdx.x * 2 + half) * LT4;
        const float4* xb4 = reinterpret_cast<const float4*>(X)
                            + (size_t)b * 2 * NN * L4 + l0q;

        // ---- stage bf16 x tile for this half ----
        for (int idx = tid; idx < NN * LT4; idx += NTHREADS) {
            int w = idx >> 5, c = idx & (LT4 - 1);
            float4 v = xb4[(size_t)w * L4 + c];
            uint2 p; p.x = f2bf2(v.y, v.x); p.y = f2bf2(v.w, v.z);
            sxb[w * 32 + c] = p;
        }
        if (half == 0) asm volatile("cp.async.wait_group 0;");
        __syncthreads();

        float4* ob4 = reinterpret_cast<float4*>(out) + (size_t)b * NN * L4 + l0q + lane;

        // row-ahead prefetch of the fp32 diagonal/passthrough vector
        float4 xw = (wg < NN) ? xb4[(size_t)wg * L4 + lane]
                              : make_float4(0.f, 0.f, 0.f, 0.f);

        for (int w = wg; w < NN; w += NWARPS) {
            // kick next row's LDG before the long LDS loops
            int wn = w + NWARPS;
            float4 xwn = xw;
            if (wn < NN) xwn = xb4[(size_t)wn * L4 + lane];

            float4 c1 = sc1[w];
            float2 c2 = sc2[w];
            float dra = b0 ? 0.f : c1.y;   // batch 0: RWa diagonal is exactly zero

            unsigned long long xw01 = pk2(xw.x, xw.y), xw23 = pk2(xw.z, xw.w);
            unsigned long long drp  = pk2(c1.x, c1.x), brp  = pk2(c1.w, c1.w);
            unsigned long long drap = pk2(dra,  dra ), brap = pk2(c2.x, c2.x);
            unsigned long long dlp  = pk2(c1.z, c1.z), bdp  = pk2(c2.y, c2.y);

            unsigned long long r01 = brp,  r23 = brp;
            unsigned long long ra01 = brap, ra23 = brap;
            unsigned long long li01 = bdp,  li23 = bdp;
            fma2(r01, drp, xw01);   fma2(r23, drp, xw23);
            fma2(ra01, drap, xw01); fma2(ra23, drap, xw23);
            fma2(li01, dlp, xw01);  fma2(li23, dlp, xw23);

            int k0 = soF[w], k1 = soF[w + 1];
            #pragma unroll 8
            for (int k = k0; k < k1; k++) {
                EF e = sef[k];                        // broadcast LDS.128 (1 wf)
                uint2 xv = *reinterpret_cast<const uint2*>(sxbase + e.noff);
                unsigned long long x01 = bf2f2(xv.x), x23 = bf2f2(xv.y);
                unsigned long long wrp  = pk2(e.wrn, e.wrn);
                unsigned long long wrap = pk2(e.wra, e.wra);
                fma2(r01, wrp, x01);   fma2(r23, wrp, x23);
                fma2(ra01, wrap, x01); fma2(ra23, wrap, x23);
            }

            k0 = soT[w]; k1 = soT[w + 1];
            #pragma unroll 8
            for (int k = k0; k < k1; k++) {
                ET e = set_[k];                       // broadcast LDS.64 (1 wf)
                uint2 xv = *reinterpret_cast<const uint2*>(sxbase + e.noff);
                unsigned long long x01 = bf2f2(xv.x), x23 = bf2f2(xv.y);
                unsigned long long wdp = pk2(e.wdc, e.wdc);
                fma2(li01, wdp, x01); fma2(li23, wdp, x23);
            }

            float r0, r1, r2, r3, a0, a1, a2, a3, l0, l1, l2, l3;
            upk2(r01, r0, r1);   upk2(r23, r2, r3);
            upk2(ra01, a0, a1);  upk2(ra23, a2, a3);
            upk2(li01, l0, l1);  upk2(li23, l2, l3);

            float4 o;
            o.x = ftanh(r0) + ftanh(a0) + l0;
            o.y = ftanh(r1) + ftanh(a1) + l1;
            o.z = ftanh(r2) + ftanh(a2) + l2;
            o.w = ftanh(r3) + ftanh(a3) + l3;
            ob4[(size_t)w * L4] = o;

            xw = xwn;
        }
        __syncthreads();   // all reads of sxb done before half=1 overwrites it
    }
}

// ---------------- launch ----------------
extern "C" void kernel_launch(void* const* d_in, const int* in_sizes, int n_in,
                              void* d_out, int out_size) {
    const float* X   = (const float*)d_in[0];
    const int*   ind = (const int*)d_in[1];
    const int*   ef  = (const int*)d_in[2];
    const int*   et  = (const int*)d_in[3];
    const float* wr  = (const float*)d_in[4];
    const float* wd  = (const float*)d_in[5];
    const float* wra = (const float*)d_in[6];
    const float* wda = (const float*)d_in[7];
    const float* br  = (const float*)d_in[8];
    const float* bd  = (const float*)d_in[9];
    const float* bra = (const float*)d_in[10];
    const float* bda = (const float*)d_in[11];
    float* out = (float*)d_out;

    const int csmem = (2 * EE + 2 * NCH * NN + 2 * (NN + 1) + 2 * NN)
                      * (int)sizeof(int);               // ~106.5 KB
    const int smem  = EE * (int)sizeof(EF)          // 27,552 EF
                    + NN * 32 * (int)sizeof(uint2)  // 52,992 bf16 tile
                    + EE * (int)sizeof(ET)          // 13,776 ET
                    + NN * (int)sizeof(float4)      //  3,312 c1
                    + NN * (int)sizeof(float2)      //  1,656 c2
                    + 2 * (NN + 1) * (int)sizeof(int); // 1,664 offsets => 100,952 B
    cudaFuncSetAttribute(rd_csr, cudaFuncAttributeMaxDynamicSharedMemorySize, csmem);
    cudaFuncSetAttribute(rd_main, cudaFuncAttributeMaxDynamicSharedMemorySize, smem);

    rd_csr<<<1, 1024, csmem>>>(ef, et);
    rd_pack<<<TT, 256>>>(wr, wd, wra, wda, br, bd, bra, bda);

    dim3 grid(LL / (LT4 * 4 * 2), BB);   // (8, 64) — two L-tiles per CTA
    rd_main<<<grid, NTHREADS, smem>>>(X, ind, out);
}

// round 13
// speedup vs baseline: 1.1983x; 1.0209x over previous
#include <cuda_runtime.h>

#define NN 207
#define EE 1722
#define TT 24
#define BB 64
#define LL 2048
#define RESV 12
#define L4 (LL / 4)      // 512 float4 per row
#define LT4 32           // float4 per L-tile (= 128 floats)
#define NTHREADS 512     // main kernel: 2 CTAs/SM (101 KB smem each)
#define NWARPS (NTHREADS / 32)
#define NCH ((EE + 31) / 32)   // 54 edge chunks of 32

// ---------------- device scratch (no allocation allowed) ----------------
// EF: {wrn, wrn, wra, noff} — duplicated -wr so LDS.128 lands the FFMA2 pair
// directly in an aligned register pair (no MOV duplication needed).
struct __align__(16) EF { float wrn0; float wrn1; float wra; int noff; };
struct __align__(8)  ET { float wdc; int noff; };

__device__ EF     g_ef[TT * EE];      // from-CSR ordered, per t (reaction gathers)
__device__ ET     g_et[TT * EE];      // to-CSR ordered, per t (diffusion gathers)
__device__ float4 g_c1[TT * NN];      // (dr, dra, dd+dda+1, br)
__device__ float2 g_c2[TT * NN];      // (bra, bd+bda)
__device__ int    g_from_off[NN + 1];
__device__ int    g_to_off[NN + 1];
__device__ int    g_eidF[EE];         // from-CSR slot -> edge id
__device__ int    g_eidT[EE];         // to-CSR slot -> edge id
__device__ int    g_noffF[EE];        // from-CSR slot -> byte off of x[to] bf16 row (node*256)
__device__ int    g_noffT[EE];        // to-CSR slot -> byte off of x[from] bf16 row

// ---------------- packed helpers ----------------
__device__ __forceinline__ unsigned long long pk2(float a, float b) {
    unsigned long long r;
    asm("mov.b64 %0, {%1, %2};" : "=l"(r) : "f"(a), "f"(b));
    return r;
}
__device__ __forceinline__ unsigned long long pkpair(unsigned a, unsigned b) {
    unsigned long long r;
    asm("mov.b64 %0, {%1, %2};" : "=l"(r) : "r"(a), "r"(b));
    return r;
}
__device__ __forceinline__ void upk2(unsigned long long v, float& a, float& b) {
    asm("mov.b64 {%0, %1}, %2;" : "=f"(a), "=f"(b) : "l"(v));
}
__device__ __forceinline__ void fma2(unsigned long long& d,
                                     unsigned long long a, unsigned long long b) {
    asm("fma.rn.f32x2 %0, %1, %2, %0;" : "+l"(d) : "l"(a), "l"(b));
}
// packed bf16 pair (hi=c1|lo=c0) -> f32x2 {lo≈c0, hi≈c1}. The hi lane reuses
// the raw word as fp32: the partner bf16's bits sit at relative 2^-16 —
// negligible vs bf16's own 2^-8 precision. Saves the AND.
__device__ __forceinline__ unsigned long long bf2f2(unsigned v) {
    unsigned long long r;
    asm("{\n\t.reg .b32 lo;\n\t"
        "shl.b32 lo, %1, 16;\n\t"
        "mov.b64 %0, {lo, %1};\n\t}" : "=l"(r) : "r"(v));
    return r;
}
// pack (c0, c1) fp32 -> bf16x2 (hi=c1, lo=c0), round-to-nearest
__device__ __forceinline__ unsigned f2bf2(float c1, float c0) {
    unsigned r;
    asm("cvt.rn.bf16x2.f32 %0, %1, %2;" : "=r"(r) : "f"(c1), "f"(c0));
    return r;
}
__device__ __forceinline__ float ftanh(float x) {
    float y;
    asm("tanh.approx.f32 %0, %1;" : "=f"(y) : "f"(x));
    return y;
}

// =====================================================================
// Prepass 1: t-independent deterministic CSR, chunk-parallel.
// TWO blocks: block 0 builds the from-CSR, block 1 the to-CSR.
// slot(i) = off[key] + chunk_base[chunk(i)][key] + rank_within_chunk.
// =====================================================================
__global__ __launch_bounds__(1024)
void rd_csr(const int* __restrict__ ef, const int* __restrict__ et) {
    extern __shared__ int sh[];
    int* key = sh;                 // [EE]
    int* oth = key + EE;           // [EE]
    int* cb  = oth + EE;           // [NCH*NN] counts -> chunk bases
    int* off = cb + NCH * NN;      // [NN+1]
    int* tot = off + NN + 1;       // [NN]

    const bool isT = (blockIdx.x != 0);
    const int* kin = isT ? et : ef;
    const int* oin = isT ? ef : et;
    int* g_eid  = isT ? g_eidT : g_eidF;
    int* g_noff = isT ? g_noffT : g_noffF;
    int* g_off  = isT ? g_to_off : g_from_off;

    const int tid = threadIdx.x;
    const int lane = tid & 31;
    const int wid  = tid >> 5;

    for (int i = tid; i < EE; i += 1024) { key[i] = kin[i]; oth[i] = oin[i]; }
    for (int i = tid; i < NCH * NN; i += 1024) cb[i] = 0;
    __syncthreads();

    // per-(chunk, node) counts — int atomics, order-independent
    for (int i = tid; i < EE; i += 1024) {
        int c = i >> 5;
        atomicAdd(&cb[c * NN + key[i]], 1);
    }
    __syncthreads();

    // per-node exclusive prefix over chunks (counts -> chunk bases)
    if (tid < NN) {
        int run = 0;
        #pragma unroll 6
        for (int c = 0; c < NCH; c++) {
            int v = cb[c * NN + tid]; cb[c * NN + tid] = run; run += v;
        }
        tot[tid] = run;
    }
    __syncthreads();

    // warp 0: exclusive scan tot -> off
    if (wid == 0) {
        int carry = 0;
        #pragma unroll
        for (int j = 0; j < (NN + 31) / 32; j++) {
            int idx = j * 32 + lane;
            int v = (idx < NN) ? tot[idx] : 0;
            int s = v;
            #pragma unroll
            for (int d = 1; d < 32; d <<= 1) {
                int u = __shfl_up_sync(0xffffffffu, s, d);
                if (lane >= d) s += u;
            }
            int tsum = __shfl_sync(0xffffffffu, s, 31);
            if (idx < NN) off[idx] = carry + s - v;
            carry += tsum;
        }
        if (lane == 0) off[NN] = carry;
    }
    __syncthreads();

    // chunk-parallel slot assignment across all 32 warps
    for (int c = wid; c < NCH; c += 32) {
        int i = c * 32 + lane;
        int f = (i < EE) ? key[i] : (NN + lane);   // distinct dummies
        unsigned m = __match_any_sync(0xffffffffu, f);
        int rank = __popc(m & ((1u << lane) - 1u));
        if (i < EE) {
            int slot = off[f] + cb[c * NN + f] + rank;
            g_eid[slot]  = i;
            g_noff[slot] = oth[i] * 256;   // byte offset of target bf16 row
        }
    }
    __syncthreads();

    if (tid <= NN) g_off[tid] = off[tid];
}

// =====================================================================
// Prepass 2: slot-parallel per-t record packing + coefficient sums.
// =====================================================================
__global__ __launch_bounds__(256)
void rd_pack(const float* __restrict__ wr,  const float* __restrict__ wd,
             const float* __restrict__ wra, const float* __restrict__ wda,
             const float* __restrict__ br,  const float* __restrict__ bd,
             const float* __restrict__ bra, const float* __restrict__ bda) {
    const int t   = blockIdx.x;
    const int tid = threadIdx.x;
    const int tE  = t * EE;
    const int tN  = t * NN;

    for (int k = tid; k < EE; k += 256) {
        int e = g_eidF[k];
        float w = -wr[tE + e];
        EF rf; rf.wrn0 = w; rf.wrn1 = w; rf.wra = wra[tE + e];
        rf.noff = g_noffF[k];
        g_ef[tE + k] = rf;
    }
    for (int k = tid; k < EE; k += 256) {
        int e = g_eidT[k];
        ET rt; rt.wdc = wda[tE + e] - wd[tE + e]; rt.noff = g_noffT[k];
        g_et[tE + k] = rt;
    }

    // per-row coefficients, deterministic bucket-order sums
    if (tid < NN) {
        const int w = tid;
        float dd1 = 1.f;
        for (int k = g_from_off[w]; k < g_from_off[w + 1]; k++) {
            int e = g_eidF[k];
            dd1 += wd[tE + e] + wda[tE + e];
        }
        float dr = 0.f, dra = 0.f;
        for (int k = g_to_off[w]; k < g_to_off[w + 1]; k++) {
            int e = g_eidT[k];
            dr += wr[tE + e]; dra += wra[tE + e];
        }
        float4 c1; c1.x = dr; c1.y = dra; c1.z = dd1; c1.w = br[tN + w];
        g_c1[tN + w] = c1;
        float2 c2; c2.x = bra[tN + w]; c2.y = bd[tN + w] + bda[tN + w];
        g_c2[tN + w] = c2;
    }
}

// =====================================================================
// Main kernel: each CTA does TWO 128-col L-tiles, records staged once
// via cp.async, bf16 gathers, fp32 diagonal terms, f32x2 FFMA2
// accumulation. ~101 KB smem -> 2 CTAs/SM.
// =====================================================================
__global__ __launch_bounds__(NTHREADS, 2)
void rd_main(const float* __restrict__ X, const int* __restrict__ ind,
             float* __restrict__ out) {
    extern __shared__ char smem_raw[];
    uint4*  sef  = reinterpret_cast<uint4*>(smem_raw);              // [EE] EF
    uint2*  sxb  = reinterpret_cast<uint2*>(sef + EE);              // [NN*32] bf16 tile
    ET*     set_ = reinterpret_cast<ET*>(sxb + NN * 32);            // [EE]
    float4* sc1  = reinterpret_cast<float4*>(set_ + EE);            // [NN]
    float2* sc2  = reinterpret_cast<float2*>(sc1 + NN);             // [NN]
    int*    soF  = reinterpret_cast<int*>(sc2 + NN);                // [NN+1]
    int*    soT  = soF + NN + 1;                                    // [NN+1]

    const int b   = blockIdx.y;
    const int t   = ind[b] / RESV;
    const int tid = threadIdx.x;
    const int lane = tid & 31;
    const int wg   = tid >> 5;
    const bool b0  = (b == 0);
    const char* sxbase = reinterpret_cast<const char*>(sxb) + lane * 8;

    // ---- stage records via cp.async ONCE for both halves ----
    {
        unsigned sefA = (unsigned)__cvta_generic_to_shared(sef);
        const char* gef = (const char*)(g_ef + t * EE);
        for (int i = tid; i < EE; i += NTHREADS)
            asm volatile("cp.async.cg.shared.global [%0], [%1], 16;"
                         :: "r"(sefA + i * 16), "l"(gef + (size_t)i * 16));
        unsigned setA = (unsigned)__cvta_generic_to_shared(set_);
        const char* get = (const char*)(g_et + t * EE);
        for (int i = tid; i < EE / 2; i += NTHREADS)   // EE even: 861 x 16 B
            asm volatile("cp.async.cg.shared.global [%0], [%1], 16;"
                         :: "r"(setA + i * 16), "l"(get + (size_t)i * 16));
        asm volatile("cp.async.commit_group;");
    }
    if (tid < NN) { sc1[tid] = g_c1[t * NN + tid]; sc2[tid] = g_c2[t * NN + tid]; }
    if (tid >= NN && tid < 2 * NN + 2) {
        int j = tid - NN;
        if (j <= NN) { soF[j] = g_from_off[j]; soT[j] = g_to_off[j]; }
    }
    if (tid == 2 * NN + 2) soT[NN] = g_to_off[NN];

    #pragma unroll 1
    for (int half = 0; half < 2; half++) {
        const int l0q = (blockIdx.x * 2 + half) * LT4;
        const float4* xb4 = reinterpret_cast<const float4*>(X)
                            + (size_t)b * 2 * NN * L4 + l0q;

        // ---- stage bf16 x tile for this half ----
        for (int idx = tid; idx < NN * LT4; idx += NTHREADS) {
            int w = idx >> 5, c = idx & (LT4 - 1);
            float4 v = xb4[(size_t)w * L4 + c];
            uint2 p; p.x = f2bf2(v.y, v.x); p.y = f2bf2(v.w, v.z);
            sxb[w * 32 + c] = p;
        }
        if (half == 0) asm volatile("cp.async.wait_group 0;");
        __syncthreads();

        float4* ob4 = reinterpret_cast<float4*>(out) + (size_t)b * NN * L4 + l0q + lane;

        // row-ahead prefetch of the fp32 diagonal/passthrough vector
        float4 xw = (wg < NN) ? xb4[(size_t)wg * L4 + lane]
                              : make_float4(0.f, 0.f, 0.f, 0.f);

        for (int w = wg; w < NN; w += NWARPS) {
            // kick next row's LDG before the long LDS loops
            int wn = w + NWARPS;
            float4 xwn = xw;
            if (wn < NN) xwn = xb4[(size_t)wn * L4 + lane];

            float4 c1 = sc1[w];
            float2 c2 = sc2[w];
            float dra = b0 ? 0.f : c1.y;   // batch 0: RWa diagonal is exactly zero

            unsigned long long xw01 = pk2(xw.x, xw.y), xw23 = pk2(xw.z, xw.w);
            unsigned long long drp  = pk2(c1.x, c1.x), brp  = pk2(c1.w, c1.w);
            unsigned long long drap = pk2(dra,  dra ), brap = pk2(c2.x, c2.x);
            unsigned long long dlp  = pk2(c1.z, c1.z), bdp  = pk2(c2.y, c2.y);

            unsigned long long r01 = brp,  r23 = brp;
            unsigned long long ra01 = brap, ra23 = brap;
            unsigned long long li01 = bdp,  li23 = bdp;
            fma2(r01, drp, xw01);   fma2(r23, drp, xw23);
            fma2(ra01, drap, xw01); fma2(ra23, drap, xw23);
            fma2(li01, dlp, xw01);  fma2(li23, dlp, xw23);

            int k0 = soF[w], k1 = soF[w + 1];
            #pragma unroll 8
            for (int k = k0; k < k1; k++) {
                uint4 e = sef[k];                     // broadcast LDS.128 (1 wf)
                unsigned long long wrp  = pkpair(e.x, e.y);   // pair alias (free)
                unsigned long long wrap = pkpair(e.z, e.z);   // 1 MOV
                uint2 xv = *reinterpret_cast<const uint2*>(sxbase + (int)e.w);
                unsigned long long x01 = bf2f2(xv.x), x23 = bf2f2(xv.y);
                fma2(r01, wrp, x01);   fma2(r23, wrp, x23);
                fma2(ra01, wrap, x01); fma2(ra23, wrap, x23);
            }

            k0 = soT[w]; k1 = soT[w + 1];
            #pragma unroll 8
            for (int k = k0; k < k1; k++) {
                ET e = set_[k];                       // broadcast LDS.64 (1 wf)
                uint2 xv = *reinterpret_cast<const uint2*>(sxbase + e.noff);
                unsigned long long x01 = bf2f2(xv.x), x23 = bf2f2(xv.y);
                unsigned long long wdp = pk2(e.wdc, e.wdc);
                fma2(li01, wdp, x01); fma2(li23, wdp, x23);
            }

            float r0, r1, r2, r3, a0, a1, a2, a3, l0, l1, l2, l3;
            upk2(r01, r0, r1);   upk2(r23, r2, r3);
            upk2(ra01, a0, a1);  upk2(ra23, a2, a3);
            upk2(li01, l0, l1);  upk2(li23, l2, l3);

            float4 o;
            o.x = ftanh(r0) + ftanh(a0) + l0;
            o.y = ftanh(r1) + ftanh(a1) + l1;
            o.z = ftanh(r2) + ftanh(a2) + l2;
            o.w = ftanh(r3) + ftanh(a3) + l3;
            ob4[(size_t)w * L4] = o;

            xw = xwn;
        }
        __syncthreads();   // all reads of sxb done before half=1 overwrites it
    }
}

// ---------------- launch ----------------
extern "C" void kernel_launch(void* const* d_in, const int* in_sizes, int n_in,
                              void* d_out, int out_size) {
    const float* X   = (const float*)d_in[0];
    const int*   ind = (const int*)d_in[1];
    const int*   ef  = (const int*)d_in[2];
    const int*   et  = (const int*)d_in[3];
    const float* wr  = (const float*)d_in[4];
    const float* wd  = (const float*)d_in[5];
    const float* wra = (const float*)d_in[6];
    const float* wda = (const float*)d_in[7];
    const float* br  = (const float*)d_in[8];
    const float* bd  = (const float*)d_in[9];
    const float* bra = (const float*)d_in[10];
    const float* bda = (const float*)d_in[11];
    float* out = (float*)d_out;

    const int csmem = (2 * EE + NCH * NN + (NN + 1) + NN) * (int)sizeof(int); // ~60 KB
    const int smem  = EE * (int)sizeof(EF)          // 27,552 EF
                    + NN * 32 * (int)sizeof(uint2)  // 52,992 bf16 tile
                    + EE * (int)sizeof(ET)          // 13,776 ET
                    + NN * (int)sizeof(float4)      //  3,312 c1
                    + NN * (int)sizeof(float2)      //  1,656 c2
                    + 2 * (NN + 1) * (int)sizeof(int); // 1,664 offsets => 100,952 B
    cudaFuncSetAttribute(rd_csr, cudaFuncAttributeMaxDynamicSharedMemorySize, csmem);
    cudaFuncSetAttribute(rd_main, cudaFuncAttributeMaxDynamicSharedMemorySize, smem);

    rd_csr<<<2, 1024, csmem>>>(ef, et);
    rd_pack<<<TT, 256>>>(wr, wd, wra, wda, br, bd, bra, bda);

    dim3 grid(LL / (LT4 * 4 * 2), BB);   // (8, 64) — two L-tiles per CTA
    rd_main<<<grid, NTHREADS, smem>>>(X, ind, out);
}

// round 14
// speedup vs baseline: 1.2286x; 1.0253x over previous
#include <cuda_runtime.h>

#define NN 207
#define EE 1722
#define TT 24
#define BB 64
#define LL 2048
#define RESV 12
#define L4 (LL / 4)      // 512 float4 per row
#define LT4 32           // float4 per L-tile (= 128 floats)
#define NTHREADS 512     // main kernel: 2 CTAs/SM (~100 KB smem each)
#define NWARPS (NTHREADS / 32)
#define NCH ((EE + 31) / 32)   // 54 edge chunks of 32
#define EEPAD 1930             // to-CSR entries incl. even-padding (EE + NN rounded even)

// ---------------- device scratch (no allocation allowed) ----------------
// EF: {wrn, wrn, wra, noff} — duplicated -wr so LDS.128 lands the FFMA2 pair
// directly in an aligned register pair.
struct __align__(16) EF { float wrn0; float wrn1; float wra; int noff; };
struct __align__(8)  ET { float wdc; int noff; };

__device__ EF     g_ef[TT * EE];         // from-CSR ordered, per t (reaction gathers)
__device__ ET     g_et[TT * EEPAD];      // to-CSR ordered, per t (diffusion gathers, even-padded)
__device__ float4 g_c1[TT * NN];         // (dr, dra, dd+dda+1, br)
__device__ float2 g_c2[TT * NN];         // (bra, bd+bda)
__device__ int    g_from_off[NN + 1];
__device__ int    g_to_off[NN + 1];      // PADDED offsets (bucket sizes rounded to even)
__device__ int    g_to_cnt[NN];          // true bucket sizes (for coefficient sums)
__device__ int    g_eidF[EE];            // from-CSR slot -> edge id
__device__ int    g_eidT[EEPAD];         // to-CSR slot -> edge id (EE = padding sentinel)
__device__ int    g_noffF[EE];           // from-CSR slot -> byte off of x[to] bf16 row (node*256)
__device__ int    g_noffT[EEPAD];        // to-CSR slot -> byte off of x[from] bf16 row

// ---------------- packed helpers ----------------
__device__ __forceinline__ unsigned long long pk2(float a, float b) {
    unsigned long long r;
    asm("mov.b64 %0, {%1, %2};" : "=l"(r) : "f"(a), "f"(b));
    return r;
}
__device__ __forceinline__ unsigned long long pkpair(unsigned a, unsigned b) {
    unsigned long long r;
    asm("mov.b64 %0, {%1, %2};" : "=l"(r) : "r"(a), "r"(b));
    return r;
}
__device__ __forceinline__ void upk2(unsigned long long v, float& a, float& b) {
    asm("mov.b64 {%0, %1}, %2;" : "=f"(a), "=f"(b) : "l"(v));
}
__device__ __forceinline__ void fma2(unsigned long long& d,
                                     unsigned long long a, unsigned long long b) {
    asm("fma.rn.f32x2 %0, %1, %2, %0;" : "+l"(d) : "l"(a), "l"(b));
}
// packed bf16 pair (hi=c1|lo=c0) -> f32x2 {lo=c0, hi=c1}  (bf16 = fp32 high bits)
// The AND is load-bearing: without it the partner bf16's bits land in mantissa
// bits 0-15 (up to 2^-7 relative — same order as bf16 rounding itself).
__device__ __forceinline__ unsigned long long bf2f2(unsigned v) {
    unsigned long long r;
    asm("{\n\t.reg .b32 lo, hi;\n\t"
        "shl.b32 lo, %1, 16;\n\t"
        "and.b32 hi, %1, 0xFFFF0000;\n\t"
        "mov.b64 %0, {lo, hi};\n\t}" : "=l"(r) : "r"(v));
    return r;
}
// pack (c0, c1) fp32 -> bf16x2 (hi=c1, lo=c0), round-to-nearest
__device__ __forceinline__ unsigned f2bf2(float c1, float c0) {
    unsigned r;
    asm("cvt.rn.bf16x2.f32 %0, %1, %2;" : "=r"(r) : "f"(c1), "f"(c0));
    return r;
}
__device__ __forceinline__ float ftanh(float x) {
    float y;
    asm("tanh.approx.f32 %0, %1;" : "=f"(y) : "f"(x));
    return y;
}

// =====================================================================
// Prepass 1: t-independent deterministic CSR, chunk-parallel.
// TWO blocks: block 0 builds the from-CSR, block 1 the to-CSR (even-padded).
// slot(i) = off[key] + chunk_base[chunk(i)][key] + rank_within_chunk.
// =====================================================================
__global__ __launch_bounds__(1024)
void rd_csr(const int* __restrict__ ef, const int* __restrict__ et) {
    extern __shared__ int sh[];
    int* key = sh;                 // [EE]
    int* oth = key + EE;           // [EE]
    int* cb  = oth + EE;           // [NCH*NN] counts -> chunk bases
    int* off = cb + NCH * NN;      // [NN+1]
    int* tot = off + NN + 1;       // [NN]

    const bool isT = (blockIdx.x != 0);
    const int* kin = isT ? et : ef;
    const int* oin = isT ? ef : et;
    int* g_eid  = isT ? g_eidT : g_eidF;
    int* g_noff = isT ? g_noffT : g_noffF;
    int* g_off  = isT ? g_to_off : g_from_off;

    const int tid = threadIdx.x;
    const int lane = tid & 31;
    const int wid  = tid >> 5;

    for (int i = tid; i < EE; i += 1024) { key[i] = kin[i]; oth[i] = oin[i]; }
    for (int i = tid; i < NCH * NN; i += 1024) cb[i] = 0;
    __syncthreads();

    // per-(chunk, node) counts — int atomics, order-independent
    for (int i = tid; i < EE; i += 1024) {
        int c = i >> 5;
        atomicAdd(&cb[c * NN + key[i]], 1);
    }
    __syncthreads();

    // per-node exclusive prefix over chunks (counts -> chunk bases)
    if (tid < NN) {
        int run = 0;
        #pragma unroll 6
        for (int c = 0; c < NCH; c++) {
            int v = cb[c * NN + tid]; cb[c * NN + tid] = run; run += v;
        }
        tot[tid] = run;
        if (isT) g_to_cnt[tid] = run;   // true count for coefficient sums
    }
    __syncthreads();

    // warp 0: exclusive scan tot -> off (T side: pad bucket sizes to even)
    if (wid == 0) {
        int carry = 0;
        #pragma unroll
        for (int j = 0; j < (NN + 31) / 32; j++) {
            int idx = j * 32 + lane;
            int v = (idx < NN) ? tot[idx] : 0;
            if (isT) v = (v + 1) & ~1;
            int s = v;
            #pragma unroll
            for (int d = 1; d < 32; d <<= 1) {
                int u = __shfl_up_sync(0xffffffffu, s, d);
                if (lane >= d) s += u;
            }
            int tsum = __shfl_sync(0xffffffffu, s, 31);
            if (idx < NN) off[idx] = carry + s - v;
            carry += tsum;
        }
        if (lane == 0) off[NN] = carry;
    }
    __syncthreads();

    // chunk-parallel slot assignment across all 32 warps
    for (int c = wid; c < NCH; c += 32) {
        int i = c * 32 + lane;
        int f = (i < EE) ? key[i] : (NN + lane);   // distinct dummies
        unsigned m = __match_any_sync(0xffffffffu, f);
        int rank = __popc(m & ((1u << lane) - 1u));
        if (i < EE) {
            int slot = off[f] + cb[c * NN + f] + rank;
            g_eid[slot]  = i;
            g_noff[slot] = oth[i] * 256;   // byte offset of target bf16 row
        }
    }
    __syncthreads();

    // T side: fill padding slots (odd-sized buckets get one inert tail entry)
    if (isT && tid < NN) {
        if (tot[tid] & 1) {
            int slot = off[tid] + tot[tid];
            g_eid[slot]  = EE;   // sentinel: pack writes wdc = 0
            g_noff[slot] = 0;
        }
    }
    __syncthreads();

    if (tid <= NN) g_off[tid] = off[tid];
}

// =====================================================================
// Prepass 2: slot-parallel per-t record packing + coefficient sums.
// =====================================================================
__global__ __launch_bounds__(512)
void rd_pack(const float* __restrict__ wr,  const float* __restrict__ wd,
             const float* __restrict__ wra, const float* __restrict__ wda,
             const float* __restrict__ br,  const float* __restrict__ bd,
             const float* __restrict__ bra, const float* __restrict__ bda) {
    const int t   = blockIdx.x;
    const int tid = threadIdx.x;
    const int tE  = t * EE;
    const int tN  = t * NN;
    const int eepT = g_to_off[NN];   // padded to-CSR length

    for (int k = tid; k < EE; k += 512) {
        int e = g_eidF[k];
        float w = -wr[tE + e];
        EF rf; rf.wrn0 = w; rf.wrn1 = w; rf.wra = wra[tE + e];
        rf.noff = g_noffF[k];
        g_ef[tE + k] = rf;
    }
    for (int k = tid; k < eepT; k += 512) {
        int e = g_eidT[k];
        ET rt; rt.wdc = (e < EE) ? (wda[tE + e] - wd[tE + e]) : 0.f;
        rt.noff = g_noffT[k];
        g_et[t * EEPAD + k] = rt;
    }

    // per-row coefficients, deterministic bucket-order sums (true counts)
    if (tid < NN) {
        const int w = tid;
        float dd1 = 1.f;
        for (int k = g_from_off[w]; k < g_from_off[w + 1]; k++) {
            int e = g_eidF[k];
            dd1 += wd[tE + e] + wda[tE + e];
        }
        float dr = 0.f, dra = 0.f;
        int k0 = g_to_off[w], k1 = k0 + g_to_cnt[w];
        for (int k = k0; k < k1; k++) {
            int e = g_eidT[k];
            dr += wr[tE + e]; dra += wra[tE + e];
        }
        float4 c1; c1.x = dr; c1.y = dra; c1.z = dd1; c1.w = br[tN + w];
        g_c1[tN + w] = c1;
        float2 c2; c2.x = bra[tN + w]; c2.y = bd[tN + w] + bda[tN + w];
        g_c2[tN + w] = c2;
    }
}

// =====================================================================
// Main kernel: each CTA does TWO 128-col L-tiles, records staged once
// via cp.async, bf16 gathers (paired ET loads), fp32 diagonal terms,
// f32x2 FFMA2 accumulation. ~100 KB smem -> 2 CTAs/SM.
// =====================================================================
__global__ __launch_bounds__(NTHREADS, 2)
void rd_main(const float* __restrict__ X, const int* __restrict__ ind,
             float* __restrict__ out) {
    extern __shared__ char smem_raw[];
    uint4*  sef  = reinterpret_cast<uint4*>(smem_raw);              // [EE] EF
    uint2*  sxb  = reinterpret_cast<uint2*>(sef + EE);              // [NN*32] bf16 tile
    ET*     set_ = reinterpret_cast<ET*>(sxb + NN * 32);            // [EEPAD]
    float4* sc1  = reinterpret_cast<float4*>(set_ + EEPAD);         // [NN]
    float2* sc2  = reinterpret_cast<float2*>(sc1 + NN);             // [NN]
    int*    soF  = reinterpret_cast<int*>(sc2 + NN);                // [NN+1]
    int*    soT  = soF + NN + 1;                                    // [NN+1]

    const int b   = blockIdx.y;
    const int t   = ind[b] / RESV;
    const int tid = threadIdx.x;
    const int lane = tid & 31;
    const int wg   = tid >> 5;
    const bool b0  = (b == 0);
    const char* sxbase = reinterpret_cast<const char*>(sxb) + lane * 8;

    // ---- stage records via cp.async ONCE for both halves ----
    {
        unsigned sefA = (unsigned)__cvta_generic_to_shared(sef);
        const char* gef = (const char*)(g_ef + t * EE);
        for (int i = tid; i < EE; i += NTHREADS)
            asm volatile("cp.async.cg.shared.global [%0], [%1], 16;"
                         :: "r"(sefA + i * 16), "l"(gef + (size_t)i * 16));
        unsigned setA = (unsigned)__cvta_generic_to_shared(set_);
        const char* get = (const char*)(g_et + t * EEPAD);
        for (int i = tid; i < EEPAD / 2; i += NTHREADS)   // 965 x 16 B
            asm volatile("cp.async.cg.shared.global [%0], [%1], 16;"
                         :: "r"(setA + i * 16), "l"(get + (size_t)i * 16));
        asm volatile("cp.async.commit_group;");
    }
    if (tid < NN) { sc1[tid] = g_c1[t * NN + tid]; sc2[tid] = g_c2[t * NN + tid]; }
    if (tid >= NN && tid < 2 * NN + 2) {
        int j = tid - NN;
        if (j <= NN) { soF[j] = g_from_off[j]; soT[j] = g_to_off[j]; }
    }
    if (tid == 2 * NN + 2) soT[NN] = g_to_off[NN];

    #pragma unroll 1
    for (int half = 0; half < 2; half++) {
        const int l0q = (blockIdx.x * 2 + half) * LT4;
        const float4* xb4 = reinterpret_cast<const float4*>(X)
                            + (size_t)b * 2 * NN * L4 + l0q;

        // ---- stage bf16 x tile for this half ----
        for (int idx = tid; idx < NN * LT4; idx += NTHREADS) {
            int w = idx >> 5, c = idx & (LT4 - 1);
            float4 v = xb4[(size_t)w * L4 + c];
            uint2 p; p.x = f2bf2(v.y, v.x); p.y = f2bf2(v.w, v.z);
            sxb[w * 32 + c] = p;
        }
        if (half == 0) asm volatile("cp.async.wait_group 0;");
        __syncthreads();

        float4* ob4 = reinterpret_cast<float4*>(out) + (size_t)b * NN * L4 + l0q + lane;
        const uint4* set4 = reinterpret_cast<const uint4*>(set_);

        // row-ahead prefetch of the fp32 diagonal/passthrough vector
        float4 xw = (wg < NN) ? xb4[(size_t)wg * L4 + lane]
                              : make_float4(0.f, 0.f, 0.f, 0.f);

        for (int w = wg; w < NN; w += NWARPS) {
            // kick next row's LDG before the long LDS loops
            int wn = w + NWARPS;
            float4 xwn = xw;
            if (wn < NN) xwn = xb4[(size_t)wn * L4 + lane];

            float4 c1 = sc1[w];
            float2 c2 = sc2[w];
            float dra = b0 ? 0.f : c1.y;   // batch 0: RWa diagonal is exactly zero

            unsigned long long xw01 = pk2(xw.x, xw.y), xw23 = pk2(xw.z, xw.w);
            unsigned long long drp  = pk2(c1.x, c1.x), brp  = pk2(c1.w, c1.w);
            unsigned long long drap = pk2(dra,  dra ), brap = pk2(c2.x, c2.x);
            unsigned long long dlp  = pk2(c1.z, c1.z), bdp  = pk2(c2.y, c2.y);

            unsigned long long r01 = brp,  r23 = brp;
            unsigned long long ra01 = brap, ra23 = brap;
            unsigned long long li01 = bdp,  li23 = bdp;
            fma2(r01, drp, xw01);   fma2(r23, drp, xw23);
            fma2(ra01, drap, xw01); fma2(ra23, drap, xw23);
            fma2(li01, dlp, xw01);  fma2(li23, dlp, xw23);

            int k0 = soF[w], k1 = soF[w + 1];
            #pragma unroll 8
            for (int k = k0; k < k1; k++) {
                uint4 e = sef[k];                     // broadcast LDS.128 (1 wf)
                unsigned long long wrp  = pkpair(e.x, e.y);   // pair alias
                unsigned long long wrap = pkpair(e.z, e.z);   // 1 MOV
                uint2 xv = *reinterpret_cast<const uint2*>(sxbase + (int)e.w);
                unsigned long long x01 = bf2f2(xv.x), x23 = bf2f2(xv.y);
                fma2(r01, wrp, x01);   fma2(r23, wrp, x23);
                fma2(ra01, wrap, x01); fma2(ra23, wrap, x23);
            }

            // to-CSR buckets are even-sized: process edge PAIRS, one LDS.128
            // record load per pair (padding entries have wdc = 0).
            k0 = soT[w] >> 1; k1 = soT[w + 1] >> 1;
            #pragma unroll 4
            for (int k = k0; k < k1; k++) {
                uint4 e = set4[k];                    // 2 ET records (1 wf)
                uint2 xv0 = *reinterpret_cast<const uint2*>(sxbase + (int)e.y);
                uint2 xv1 = *reinterpret_cast<const uint2*>(sxbase + (int)e.w);
                unsigned long long wd0 = pkpair(e.x, e.x);
                unsigned long long wd1 = pkpair(e.z, e.z);
                fma2(li01, wd0, bf2f2(xv0.x)); fma2(li23, wd0, bf2f2(xv0.y));
                fma2(li01, wd1, bf2f2(xv1.x)); fma2(li23, wd1, bf2f2(xv1.y));
            }

            float r0, r1, r2, r3, a0, a1, a2, a3, l0, l1, l2, l3;
            upk2(r01, r0, r1);   upk2(r23, r2, r3);
            upk2(ra01, a0, a1);  upk2(ra23, a2, a3);
            upk2(li01, l0, l1);  upk2(li23, l2, l3);

            float4 o;
            o.x = ftanh(r0) + ftanh(a0) + l0;
            o.y = ftanh(r1) + ftanh(a1) + l1;
            o.z = ftanh(r2) + ftanh(a2) + l2;
            o.w = ftanh(r3) + ftanh(a3) + l3;
            ob4[(size_t)w * L4] = o;

            xw = xwn;
        }
        __syncthreads();   // all reads of sxb done before half=1 overwrites it
    }
}

// ---------------- launch ----------------
extern "C" void kernel_launch(void* const* d_in, const int* in_sizes, int n_in,
                              void* d_out, int out_size) {
    const float* X   = (const float*)d_in[0];
    const int*   ind = (const int*)d_in[1];
    const int*   ef  = (const int*)d_in[2];
    const int*   et  = (const int*)d_in[3];
    const float* wr  = (const float*)d_in[4];
    const float* wd  = (const float*)d_in[5];
    const float* wra = (const float*)d_in[6];
    const float* wda = (const float*)d_in[7];
    const float* br  = (const float*)d_in[8];
    const float* bd  = (const float*)d_in[9];
    const float* bra = (const float*)d_in[10];
    const float* bda = (const float*)d_in[11];
    float* out = (float*)d_out;

    const int csmem = (2 * EE + NCH * NN + (NN + 1) + NN) * (int)sizeof(int); // ~60 KB
    const int smem  = EE * (int)sizeof(EF)          // 27,552 EF
                    + NN * 32 * (int)sizeof(uint2)  // 52,992 bf16 tile
                    + EEPAD * (int)sizeof(ET)       // 15,440 ET (padded)
                    + NN * (int)sizeof(float4)      //  3,312 c1
                    + NN * (int)sizeof(float2)      //  1,656 c2
                    + 2 * (NN + 1) * (int)sizeof(int); // 1,664 offsets => 102,616 B
    cudaFuncSetAttribute(rd_csr, cudaFuncAttributeMaxDynamicSharedMemorySize, csmem);
    cudaFuncSetAttribute(rd_main, cudaFuncAttributeMaxDynamicSharedMemorySize, smem);

    rd_csr<<<2, 1024, csmem>>>(ef, et);
    rd_pack<<<TT, 512>>>(wr, wd, wra, wda, br, bd, bra, bda);

    dim3 grid(LL / (LT4 * 4 * 2), BB);   // (8, 64) — two L-tiles per CTA
    rd_main<<<grid, NTHREADS, smem>>>(X, ind, out);
}